// round 7
// baseline (speedup 1.0000x reference)
#include <cuda_runtime.h>

#define NODE_TYPE 8
#define HIST   24
#define SKIP   256
#define ENDC   128
#define KSZ    13
#define FUT    12
#define OUTD   2
#define GROUP  16
#define MAXN   4096
#define THREADS 256

// ---------------- binning scratch (device globals; no allocation) ----------------
__device__ int g_cnt[NODE_TYPE];
__device__ int g_order[NODE_TYPE * MAXN];

__global__ void reset_kernel() {
    if (threadIdx.x < NODE_TYPE) g_cnt[threadIdx.x] = 0;
}

__global__ void bin_kernel(const int* __restrict__ labels, int n) {
    int i = blockIdx.x * blockDim.x + threadIdx.x;
    if (i < n) {
        int lb = labels[i];
        int p  = atomicAdd(&g_cnt[lb], 1);
        g_order[lb * MAXN + p] = i;
    }
}

// Packed f32x2 FMA (sm_100+). PTX-only; ptxas never emits it from C++.
__device__ __forceinline__ unsigned long long ffma2(unsigned long long a,
                                                    unsigned long long b,
                                                    unsigned long long c) {
    unsigned long long d;
    asm("fma.rn.f32x2 %0, %1, %2, %3;" : "=l"(d) : "l"(a), "l"(b), "l"(c));
    return d;
}
__device__ __forceinline__ float lo32(unsigned long long v) {
    return __uint_as_float((unsigned)(v & 0xffffffffull));
}
__device__ __forceinline__ float hi32(unsigned long long v) {
    return __uint_as_float((unsigned)(v >> 32));
}

// CTA = (label, tile of GROUP same-label nodes). 256 threads:
//   ch = tid & 127 (hidden channel), dh = tid >> 7 (d-half: 128 of 256 inputs).
// Thread holds W1[lbl][ch][dh*128 .. +128) in registers for the CTA lifetime.
// Mainloop smem traffic = broadcast x reads only.
// Static smem only (~37.6 KB): hs aliases xs (x fully consumed before hs is written).
__global__ __launch_bounds__(THREADS, 1)
void tcnn_main(const float* __restrict__ x,
               const float* __restrict__ W1, const float* __restrict__ b1,
               const float* __restrict__ W2, const float* __restrict__ b2,
               float* __restrict__ out, int tilesPerLabel) {
    __shared__ __align__(16) float xs[HIST * SKIP];          // 24 KB; hs aliases front 12 KB
    __shared__ __align__(16) float w2s[OUTD * ENDC * KSZ];   // 13 KB
    __shared__ float b2s[OUTD];
    __shared__ float red[4][FUT * OUTD];
    float* hs = xs;                                          // 24*128 floats, aliased

    const int lbl  = blockIdx.x / tilesPerLabel;
    const int tile = blockIdx.x % tilesPerLabel;
    const int cnt  = g_cnt[lbl];
    const int base = tile * GROUP;
    if (base >= cnt) return;                    // uniform early exit (before any barrier)
    const int nn = min(GROUP, cnt - base);

    const int tid = threadIdx.x;
    const int ch  = tid & (ENDC - 1);
    const int dh  = tid >> 7;                   // 0 or 1 (constant per warp)
    const int l   = tid & 31;
    const int w   = tid >> 5;

    // ---- W1 slice -> registers (64 f32x2 = 128 regs), once per CTA ----
    unsigned long long wp[64];
    {
        const ulonglong2* wsrc = reinterpret_cast<const ulonglong2*>(
            W1 + ((size_t)lbl * ENDC + ch) * SKIP + dh * 128);
        #pragma unroll
        for (int i = 0; i < 32; ++i) {
            ulonglong2 v = wsrc[i];
            wp[2 * i] = v.x; wp[2 * i + 1] = v.y;
        }
    }
    const float bias1 = b1[lbl * ENDC + ch];

    // ---- W2 / b2 -> smem, once per CTA ----
    for (int i = tid; i < OUTD * ENDC * KSZ; i += THREADS)
        w2s[i] = W2[(size_t)lbl * OUTD * ENDC * KSZ + i];
    if (tid < OUTD) b2s[tid] = b2[lbl * OUTD + tid];

    // ================= node loop =================
    for (int j = 0; j < nn; ++j) {
        const int node = g_order[lbl * MAXN + base + j];
        __syncthreads();                        // prior node fully consumed (and W2 ready)

        // ---- x -> smem with relu (coalesced float4) ----
        const float4* xg  = reinterpret_cast<const float4*>(x + (size_t)node * (HIST * SKIP));
        float4*       xs4 = reinterpret_cast<float4*>(xs);
        #pragma unroll
        for (int i = 0; i < (HIST * SKIP / 4) / THREADS; ++i) {   // 6
            float4 v = xg[tid + i * THREADS];
            v.x = fmaxf(v.x, 0.f); v.y = fmaxf(v.y, 0.f);
            v.z = fmaxf(v.z, 0.f); v.w = fmaxf(v.w, 0.f);
            xs4[tid + i * THREADS] = v;
        }
        __syncthreads();

        // ---- stage 1: W in regs, x broadcast from smem ----
        float valr[HIST];
        #pragma unroll
        for (int tg = 0; tg < HIST / 6; ++tg) {         // 4 groups of 6 timesteps
            unsigned long long acc[6] = {0, 0, 0, 0, 0, 0};
            #pragma unroll
            for (int i = 0; i < 32; ++i) {              // 32 x ulonglong2 = 128 d-values
                ulonglong2 xv[6];
                #pragma unroll
                for (int tt = 0; tt < 6; ++tt)          // uniform addr -> LDS broadcast
                    xv[tt] = *reinterpret_cast<const ulonglong2*>(
                        xs + (tg * 6 + tt) * SKIP + dh * 128 + i * 4);
                #pragma unroll
                for (int tt = 0; tt < 6; ++tt)
                    acc[tt] = ffma2(wp[2 * i + 1], xv[tt].y,
                              ffma2(wp[2 * i],     xv[tt].x, acc[tt]));
            }
            #pragma unroll
            for (int tt = 0; tt < 6; ++tt)
                valr[tg * 6 + tt] = lo32(acc[tt]) + hi32(acc[tt]);
        }
        __syncthreads();                        // ALL x reads done before hs (aliased) writes

        // combine d-halves through smem
        if (dh == 1) {
            #pragma unroll
            for (int t = 0; t < HIST; ++t) hs[t * ENDC + ch] = valr[t];
        }
        __syncthreads();
        if (dh == 0) {
            #pragma unroll
            for (int t = 0; t < HIST; ++t)
                hs[t * ENDC + ch] = fmaxf(valr[t] + hs[t * ENDC + ch] + bias1, 0.f);
        }
        __syncthreads();

        // ---- stage 2 on threads 0-127 (warps 0-3) ----
        if (dh == 0) {
            float ht[HIST];
            #pragma unroll
            for (int t = 0; t < HIST; ++t) ht[t] = hs[t * ENDC + ch];

            float p[FUT * OUTD];
            #pragma unroll
            for (int q = 0; q < FUT * OUTD; ++q) p[q] = 0.f;

            #pragma unroll
            for (int k = 0; k < KSZ; ++k) {
                float wa = w2s[(0 * ENDC + ch) * KSZ + k];   // stride 13 ⊥ 32 banks
                float wb = w2s[(1 * ENDC + ch) * KSZ + k];
                #pragma unroll
                for (int f = 0; f < FUT; ++f) {
                    p[f * 2 + 0] = fmaf(ht[f + k], wa, p[f * 2 + 0]);
                    p[f * 2 + 1] = fmaf(ht[f + k], wb, p[f * 2 + 1]);
                }
            }
            #pragma unroll
            for (int q = 0; q < FUT * OUTD; ++q) {
                float v = p[q];
                #pragma unroll
                for (int off = 16; off; off >>= 1)
                    v += __shfl_xor_sync(0xffffffffu, v, off);
                p[q] = v;
            }
            if (l == 0) {
                #pragma unroll
                for (int q = 0; q < FUT * OUTD; ++q) red[w][q] = p[q];
            }
        }
        __syncthreads();

        if (tid < FUT * OUTD)
            out[(size_t)node * (FUT * OUTD) + tid] =
                red[0][tid] + red[1][tid] + red[2][tid] + red[3][tid] + b2s[tid & 1];
    }
}

extern "C" void kernel_launch(void* const* d_in, const int* in_sizes, int n_in,
                              void* d_out, int out_size) {
    const float* x      = (const float*)d_in[0];
    const int*   labels = (const int*)  d_in[1];
    const float* W1     = (const float*)d_in[2];
    const float* b1     = (const float*)d_in[3];
    const float* W2     = (const float*)d_in[4];
    const float* b2     = (const float*)d_in[5];
    float* out = (float*)d_out;

    int n = in_sizes[1];                 // B*N nodes
    if (n > MAXN) n = MAXN;
    int tiles = (n + GROUP - 1) / GROUP; // covers worst-case single-label bin

    reset_kernel<<<1, 32>>>();
    bin_kernel<<<(n + 255) / 256, 256>>>(labels, n);
    tcnn_main<<<NODE_TYPE * tiles, THREADS>>>(x, W1, b1, W2, b2, out, tiles);
}

// round 9
// speedup vs baseline: 1.4455x; 1.4455x over previous
#include <cuda_runtime.h>
#include <cuda_fp16.h>
#include <cstdint>

#define NODE_TYPE 8
#define HIST   24
#define SKIP   256
#define ENDC   128
#define KSZ    13
#define FUT    12
#define OUTD   2
#define G      4                   // nodes per CTA
#define NCOL   (G * HIST)          // 96 = GEMM N
#define NTILES (NCOL / 8)          // 12 n8-tiles
#define KC     16                  // K per chunk = one m16n8k16 step
#define NKC    (SKIP / KC)         // 16
#define MAXN   4096
#define THREADS 128

// ---------------- binning scratch ----------------
__device__ int g_cnt[NODE_TYPE];
__device__ int g_order[NODE_TYPE * MAXN];

__global__ void reset_kernel() {
    if (threadIdx.x < NODE_TYPE) g_cnt[threadIdx.x] = 0;
}
__global__ void bin_kernel(const int* __restrict__ labels, int n) {
    int i = blockIdx.x * blockDim.x + threadIdx.x;
    if (i < n) {
        int lb = labels[i];
        int p  = atomicAdd(&g_cnt[lb], 1);
        g_order[lb * MAXN + p] = i;
    }
}

// ---------------- helpers ----------------
static __device__ __forceinline__ uint32_t smem_u32(const void* p) {
    uint32_t a;
    asm("{ .reg .u64 t; cvta.to.shared.u64 t, %1; cvt.u32.u64 %0, t; }" : "=r"(a) : "l"(p));
    return a;
}
// fp16 split of 2 floats: hi = rn(v), lo = rn(v - hi). Packed half2 words.
static __device__ __forceinline__ void split2(float a, float b, uint32_t& hi, uint32_t& lo) {
    __half2 h = __floats2half2_rn(a, b);
    float2 hf = __half22float2(h);
    __half2 l = __floats2half2_rn(a - hf.x, b - hf.y);
    hi = *reinterpret_cast<uint32_t*>(&h);
    lo = *reinterpret_cast<uint32_t*>(&l);
}
static __device__ __forceinline__ void ldsm_x4(uint32_t* r, uint32_t addr) {
    asm volatile("ldmatrix.sync.aligned.m8n8.x4.shared.b16 {%0,%1,%2,%3}, [%4];"
                 : "=r"(r[0]), "=r"(r[1]), "=r"(r[2]), "=r"(r[3]) : "r"(addr));
}
static __device__ __forceinline__ void ldsm_x2(uint32_t* r, uint32_t addr) {
    asm volatile("ldmatrix.sync.aligned.m8n8.x2.shared.b16 {%0,%1}, [%2];"
                 : "=r"(r[0]), "=r"(r[1]) : "r"(addr));
}
static __device__ __forceinline__ void mma16816(float* d, const uint32_t* a, const uint32_t* b) {
    asm volatile("mma.sync.aligned.m16n8k16.row.col.f32.f16.f16.f32 "
                 "{%0,%1,%2,%3}, {%4,%5,%6,%7}, {%8,%9}, {%0,%1,%2,%3};"
                 : "+f"(d[0]), "+f"(d[1]), "+f"(d[2]), "+f"(d[3])
                 : "r"(a[0]), "r"(a[1]), "r"(a[2]), "r"(a[3]), "r"(b[0]), "r"(b[1]));
}

// CTA = (label, group of 4 same-label nodes).
// Stage 1 GEMM on legacy HMMA: D[ch][n] = sum_d W1[lbl][ch][d] * relu(x)[n][d],
// M=128 N=96 K=256, fp16 3-term split (hh + h*l + l*h), fp32 accumulate.
// Warp w owns m16-tiles {16w, 64+16w}; B fragments shared across both tiles.
__global__ __launch_bounds__(THREADS)
void tcnn_hmma(const float* __restrict__ x,
               const float* __restrict__ W1, const float* __restrict__ b1,
               const float* __restrict__ W2, const float* __restrict__ b2,
               float* __restrict__ out, int tilesPerLabel) {
    // K-chunk staging (fp16 split terms), b32 words: row stride = KC/2 = 8
    __shared__ __align__(16) uint32_t whu[ENDC * 8];   // 4 KB
    __shared__ __align__(16) uint32_t wlu[ENDC * 8];   // 4 KB
    __shared__ __align__(16) uint32_t xhu[NCOL * 8];   // 3 KB
    __shared__ __align__(16) uint32_t xlu[NCOL * 8];   // 3 KB
    __shared__ __align__(16) float hs[HIST * ENDC];    // 12 KB hidden slab (per node)
    __shared__ float red[4][FUT * OUTD];

    const int lbl  = blockIdx.x / tilesPerLabel;
    const int tile = blockIdx.x % tilesPerLabel;
    const int cnt  = g_cnt[lbl];
    const int base = tile * G;
    if (base >= cnt) return;                         // uniform early exit

    int ndv[G];
    #pragma unroll
    for (int i = 0; i < G; ++i)
        ndv[i] = (base + i < cnt) ? g_order[lbl * MAXN + base + i] : -1;

    const int tid  = threadIdx.x;
    const int wid  = tid >> 5;
    const int lane = tid & 31;
    const int gq   = lane >> 2;                      // group-of-4 id (0..7)
    const int tq   = lane & 3;                       // thread-in-group (0..3)
    const int mt0  = wid * 16;                       // m-tiles per warp
    const int mt1  = 64 + wid * 16;

    const uint32_t whb = smem_u32(whu), wlb = smem_u32(wlu);
    const uint32_t xhb = smem_u32(xhu), xlb = smem_u32(xlu);

    // ldmatrix per-lane offsets (halves)
    const int q    = lane >> 3, r = lane & 7;
    const int aoff = ((q & 1) * 8 + r) * KC + (q >> 1) * 8;      // A: x4 quads
    const int li   = lane & 15;
    const int boff = (li & 7) * KC + (li >> 3) * 8;              // B: x2 quads

    float acc[2][NTILES][4];
    #pragma unroll
    for (int m = 0; m < 2; ++m)
        #pragma unroll
        for (int nt = 0; nt < NTILES; ++nt)
            #pragma unroll
            for (int c = 0; c < 4; ++c) acc[m][nt][c] = 0.f;

    const float* w1p = W1 + (size_t)lbl * ENDC * SKIP;

    // ================= K-chunk mainloop =================
    for (int kc = 0; kc < NKC; ++kc) {
        __syncthreads();                             // smem free (prev chunk consumed)

        // --- W chunk: 128 rows x 16 cols fp32 -> split fp16 ---
        #pragma unroll
        for (int i = 0; i < 4; ++i) {
            int f = tid + i * THREADS;               // 0..511
            int row = f >> 2, c4 = f & 3;
            float4 v = *reinterpret_cast<const float4*>(
                w1p + (size_t)row * SKIP + kc * KC + c4 * 4);
            uint32_t h0, l0, h1, l1;
            split2(v.x, v.y, h0, l0);
            split2(v.z, v.w, h1, l1);
            whu[row * 8 + c4 * 2]     = h0;
            whu[row * 8 + c4 * 2 + 1] = h1;
            wlu[row * 8 + c4 * 2]     = l0;
            wlu[row * 8 + c4 * 2 + 1] = l1;
        }
        // --- x chunk: 96 rows (node*24+t) x 16 cols, relu + split ---
        #pragma unroll
        for (int i = 0; i < 3; ++i) {
            int f = tid + i * THREADS;               // 0..383
            int row = f >> 2, c4 = f & 3;
            int ln = row / HIST, tt = row - ln * HIST;
            int nd = ndv[ln];
            float4 v = make_float4(0.f, 0.f, 0.f, 0.f);
            if (nd >= 0) {
                v = *reinterpret_cast<const float4*>(
                    x + ((size_t)nd * HIST + tt) * SKIP + kc * KC + c4 * 4);
                v.x = fmaxf(v.x, 0.f); v.y = fmaxf(v.y, 0.f);
                v.z = fmaxf(v.z, 0.f); v.w = fmaxf(v.w, 0.f);
            }
            uint32_t h0, l0, h1, l1;
            split2(v.x, v.y, h0, l0);
            split2(v.z, v.w, h1, l1);
            xhu[row * 8 + c4 * 2]     = h0;
            xhu[row * 8 + c4 * 2 + 1] = h1;
            xlu[row * 8 + c4 * 2]     = l0;
            xlu[row * 8 + c4 * 2 + 1] = l1;
        }
        __syncthreads();

        // --- A fragments for both m-tiles, both terms ---
        uint32_t ah[2][4], al[2][4];
        ldsm_x4(ah[0], whb + (uint32_t)(aoff + mt0 * KC) * 2);
        ldsm_x4(ah[1], whb + (uint32_t)(aoff + mt1 * KC) * 2);
        ldsm_x4(al[0], wlb + (uint32_t)(aoff + mt0 * KC) * 2);
        ldsm_x4(al[1], wlb + (uint32_t)(aoff + mt1 * KC) * 2);

        // --- N loop: B frags shared across the two m-tiles ---
        #pragma unroll
        for (int nt = 0; nt < NTILES; ++nt) {
            uint32_t bh[2], bl[2];
            ldsm_x2(bh, xhb + (uint32_t)(boff + nt * 8 * KC) * 2);
            ldsm_x2(bl, xlb + (uint32_t)(boff + nt * 8 * KC) * 2);
            mma16816(acc[0][nt], ah[0], bh);
            mma16816(acc[0][nt], ah[0], bl);
            mma16816(acc[0][nt], al[0], bh);
            mma16816(acc[1][nt], ah[1], bh);
            mma16816(acc[1][nt], ah[1], bl);
            mma16816(acc[1][nt], al[1], bh);
        }
    }

    // ================= epilogue =================
    // biases for this thread's 4 channels
    float bias[2][2];
    bias[0][0] = b1[lbl * ENDC + mt0 + gq];
    bias[0][1] = b1[lbl * ENDC + mt0 + 8 + gq];
    bias[1][0] = b1[lbl * ENDC + mt1 + gq];
    bias[1][1] = b1[lbl * ENDC + mt1 + 8 + gq];

    // stage-2 weights for thread's conv channel (ch = tid)
    float wa[KSZ], wb[KSZ];
    const float* p2 = W2 + ((size_t)lbl * OUTD * ENDC + tid) * KSZ;
    #pragma unroll
    for (int k = 0; k < KSZ; ++k) {
        wa[k] = __ldg(p2 + k);
        wb[k] = __ldg(p2 + (size_t)ENDC * KSZ + k);
    }
    const float bo0 = __ldg(b2 + lbl * OUTD);
    const float bo1 = __ldg(b2 + lbl * OUTD + 1);

    for (int ln = 0; ln < G; ++ln) {
        __syncthreads();                              // hs free (prev node consumed)
        // write h slab: D frag (g, 2t)(g,2t+1)(g+8,2t)(g+8,2t+1) per n8-tile
        #pragma unroll
        for (int m = 0; m < 2; ++m) {
            int chA = (m ? mt1 : mt0) + gq;
            int chB = chA + 8;
            #pragma unroll
            for (int j = 0; j < 3; ++j) {
                int nt  = ln * 3 + j;
                int tt0 = j * 8 + 2 * tq;
                hs[tt0 * ENDC + chA]       = fmaxf(acc[m][nt][0] + bias[m][0], 0.f);
                hs[(tt0 + 1) * ENDC + chA] = fmaxf(acc[m][nt][1] + bias[m][0], 0.f);
                hs[tt0 * ENDC + chB]       = fmaxf(acc[m][nt][2] + bias[m][1], 0.f);
                hs[(tt0 + 1) * ENDC + chB] = fmaxf(acc[m][nt][3] + bias[m][1], 0.f);
            }
        }
        __syncthreads();

        // stage-2 conv: thread = channel (128 threads)
        float ht[HIST];
        #pragma unroll
        for (int t = 0; t < HIST; ++t) ht[t] = hs[t * ENDC + tid];  // conflict-free

        float p[FUT * OUTD];
        #pragma unroll
        for (int qd = 0; qd < FUT * OUTD; ++qd) p[qd] = 0.f;
        #pragma unroll
        for (int k = 0; k < KSZ; ++k) {
            #pragma unroll
            for (int ff = 0; ff < FUT; ++ff) {
                p[ff * 2 + 0] = fmaf(ht[ff + k], wa[k], p[ff * 2 + 0]);
                p[ff * 2 + 1] = fmaf(ht[ff + k], wb[k], p[ff * 2 + 1]);
            }
        }
        #pragma unroll
        for (int qd = 0; qd < FUT * OUTD; ++qd) {
            float v = p[qd];
            #pragma unroll
            for (int off = 16; off; off >>= 1) v += __shfl_xor_sync(0xffffffffu, v, off);
            p[qd] = v;
        }
        if (lane == 0) {
            #pragma unroll
            for (int qd = 0; qd < FUT * OUTD; ++qd) red[wid][qd] = p[qd];
        }
        __syncthreads();

        if (tid < FUT * OUTD && ndv[ln] >= 0) {
            out[(size_t)ndv[ln] * (FUT * OUTD) + tid] =
                red[0][tid] + red[1][tid] + red[2][tid] + red[3][tid]
                + ((tid & 1) ? bo1 : bo0);
        }
    }
}

extern "C" void kernel_launch(void* const* d_in, const int* in_sizes, int n_in,
                              void* d_out, int out_size) {
    const float* x      = (const float*)d_in[0];
    const int*   labels = (const int*)  d_in[1];
    const float* W1     = (const float*)d_in[2];
    const float* b1     = (const float*)d_in[3];
    const float* W2     = (const float*)d_in[4];
    const float* b2     = (const float*)d_in[5];
    float* out = (float*)d_out;

    int n = in_sizes[1];                       // B*N nodes = 4096
    if (n > MAXN) n = MAXN;
    int tiles = (n + G - 1) / G;               // covers worst-case single-label bin

    reset_kernel<<<1, 32>>>();
    bin_kernel<<<(n + 255) / 256, 256>>>(labels, n);
    tcnn_hmma<<<NODE_TYPE * tiles, THREADS>>>(x, W1, b1, W2, b2, out, tiles);
}